// round 11
// baseline (speedup 1.0000x reference)
#include <cuda_runtime.h>
#include <cuda_fp16.h>
#include <math.h>

#define NN 150000
#define UU 100000
#define II 50000
#define DD 64
#define EE 2000000
#define LL 3
#define SCAN_B 1024
#define NBLK ((NN + SCAN_B - 1) / SCAN_B)   // 147

// bit-cast helpers (no __half2_as_uint in this toolkit)
__device__ __forceinline__ unsigned int h2_as_u32(__half2 h) {
    return *reinterpret_cast<unsigned int*>(&h);
}
__device__ __forceinline__ __half2 u32_as_h2(unsigned int u) {
    return *reinterpret_cast<__half2*>(&u);
}

// -------- device scratch (no allocations allowed) --------
__device__ float g_curA[NN * DD];
__device__ float g_curB[NN * DD];
__device__ float g_curS[NN * DD];        // dis ⊙ cur (layer1 gather operand)
__device__ float g_gnn[NN * DD];
__device__ uint2 g_pack[NN * 32];        // per lane: {half2 gnn_norm, half2 cur_old}
__device__ float g_invn[NN];
__device__ float g_dis[NN];
__device__ int   g_deg[NN];
__device__ int   g_rowptr[NN + 1];
__device__ int   g_cursor[NN];
__device__ int   g_ecol[EE];
__device__ int   g_bsum[NBLK + 1];
__device__ int   g_boff[NBLK + 1];

// ---------------- setup kernels ----------------

__global__ void hist_kernel(const int* __restrict__ rows) {
    int e = blockIdx.x * blockDim.x + threadIdx.x;
    if (e < EE) atomicAdd(&g_deg[rows[e]], 1);
}

__global__ void scan1_kernel() {
    __shared__ int s[SCAN_B];
    int i = blockIdx.x * SCAN_B + threadIdx.x;
    int v = (i < NN) ? g_deg[i] : 0;
    if (i < NN) g_dis[i] = v > 0 ? rsqrtf((float)v) : 0.f;
    s[threadIdx.x] = v;
    __syncthreads();
    #pragma unroll
    for (int off = 1; off < SCAN_B; off <<= 1) {
        int t = (threadIdx.x >= off) ? s[threadIdx.x - off] : 0;
        __syncthreads();
        s[threadIdx.x] += t;
        __syncthreads();
    }
    if (i < NN) g_rowptr[i + 1] = s[threadIdx.x];
    if (threadIdx.x == SCAN_B - 1) g_bsum[blockIdx.x] = s[SCAN_B - 1];
}

__global__ void scan2_kernel() {
    __shared__ int s[256];
    int t = threadIdx.x;
    int v = (t < NBLK) ? g_bsum[t] : 0;
    s[t] = v;
    __syncthreads();
    #pragma unroll
    for (int off = 1; off < 256; off <<= 1) {
        int x = (t >= off) ? s[t - off] : 0;
        __syncthreads();
        s[t] += x;
        __syncthreads();
    }
    if (t < NBLK) g_boff[t] = s[t] - v;
}

__global__ void scan3_kernel() {
    int i = blockIdx.x * blockDim.x + threadIdx.x;
    if (i == 0) g_rowptr[0] = 0;
    if (i < NN) {
        int fin = g_rowptr[i + 1] + g_boff[i / SCAN_B];
        g_rowptr[i + 1] = fin;
        g_cursor[i] = fin - g_deg[i];
    }
}

__global__ void scatter_kernel(const int* __restrict__ rows, const int* __restrict__ cols) {
    int e = blockIdx.x * blockDim.x + threadIdx.x;
    if (e >= EE) return;
    int r = rows[e];
    int pos = atomicAdd(&g_cursor[r], 1);
    g_ecol[pos] = cols[e];
}

__global__ void init_kernel(const float* __restrict__ user_emb,
                            const float* __restrict__ item_emb,
                            float* __restrict__ out) {
    int i = blockIdx.x * blockDim.x + threadIdx.x;
    if (i < NN * DD) {
        float v = (i < UU * DD) ? user_emb[i] : item_emb[i - UU * DD];
        g_curA[i] = v;
        g_curS[i] = v * g_dis[i >> 6];
        out[i] = v;
    }
}

// ---------------- per-layer kernels ----------------

// warp-per-row gather-sum: gnn[r] = dis[r] * sum_e curS[c_e]
// epilogue: invn + packed {gnn_norm fp16, cur_old fp16}
__global__ void __launch_bounds__(256)
layer1_kernel(const float* __restrict__ curS, const float* __restrict__ cur_old) {
    int w = (blockIdx.x * blockDim.x + threadIdx.x) >> 5;
    int lane = threadIdx.x & 31;
    if (w >= NN) return;
    int start = g_rowptr[w];
    int end   = g_rowptr[w + 1];
    float ax0 = 0.f, ay0 = 0.f, ax1 = 0.f, ay1 = 0.f;
    int j = start;
    for (; j + 3 < end; j += 4) {
        int c0 = __ldg(g_ecol + j);
        int c1 = __ldg(g_ecol + j + 1);
        int c2 = __ldg(g_ecol + j + 2);
        int c3 = __ldg(g_ecol + j + 3);
        float2 v0 = __ldg(((const float2*)(curS + (size_t)c0 * DD)) + lane);
        float2 v1 = __ldg(((const float2*)(curS + (size_t)c1 * DD)) + lane);
        float2 v2 = __ldg(((const float2*)(curS + (size_t)c2 * DD)) + lane);
        float2 v3 = __ldg(((const float2*)(curS + (size_t)c3 * DD)) + lane);
        ax0 += v0.x + v2.x;  ay0 += v0.y + v2.y;
        ax1 += v1.x + v3.x;  ay1 += v1.y + v3.y;
    }
    for (; j < end; j++) {
        int c = __ldg(g_ecol + j);
        float2 v = __ldg(((const float2*)(curS + (size_t)c * DD)) + lane);
        ax0 += v.x;  ay0 += v.y;
    }
    float dr = g_dis[w];
    float ax = (ax0 + ax1) * dr;
    float ay = (ay0 + ay1) * dr;
    ((float2*)(g_gnn + (size_t)w * DD))[lane] = make_float2(ax, ay);
    float ss = ax * ax + ay * ay;
    #pragma unroll
    for (int o = 16; o > 0; o >>= 1) ss += __shfl_xor_sync(0xFFFFFFFFu, ss, o);
    float inv = 1.0f / fmaxf(sqrtf(ss), 1e-12f);
    if (lane == 0) g_invn[w] = inv;
    float2 cv = ((const float2*)(cur_old + (size_t)w * DD))[lane];
    uint2 p;
    p.x = h2_as_u32(__floats2half2_rn(ax * inv, ay * inv));
    p.y = h2_as_u32(__floats2half2_rn(cv.x, cv.y));
    g_pack[(size_t)w * 32 + lane] = p;
}

// warp-per-row fused: scores + rowsum + fine + finalize — ONE 8B gather per edge/lane
__global__ void __launch_bounds__(256)
layer2_kernel(float* __restrict__ cur_new,
              float* __restrict__ out, int layer) {
    int w = (blockIdx.x * blockDim.x + threadIdx.x) >> 5;
    int lane = threadIdx.x & 31;
    if (w >= NN) return;
    int start = g_rowptr[w];
    int end   = g_rowptr[w + 1];
    float2 gfull = ((const float2*)(g_gnn + (size_t)w * DD))[lane];
    float invr = g_invn[w];
    float grx = gfull.x * invr, gry = gfull.y * invr;

    float rowsum = 0.f, fx = 0.f, fy = 0.f;
    int j = start;
    for (; j + 3 < end; j += 4) {
        int c0 = __ldg(g_ecol + j);
        int c1 = __ldg(g_ecol + j + 1);
        int c2 = __ldg(g_ecol + j + 2);
        int c3 = __ldg(g_ecol + j + 3);
        uint2 p0 = __ldg(g_pack + (size_t)c0 * 32 + lane);
        uint2 p1 = __ldg(g_pack + (size_t)c1 * 32 + lane);
        uint2 p2 = __ldg(g_pack + (size_t)c2 * 32 + lane);
        uint2 p3 = __ldg(g_pack + (size_t)c3 * 32 + lane);
        float2 q0 = __half22float2(u32_as_h2(p0.x));
        float2 q1 = __half22float2(u32_as_h2(p1.x));
        float2 q2 = __half22float2(u32_as_h2(p2.x));
        float2 q3 = __half22float2(u32_as_h2(p3.x));
        float d0 = grx * q0.x + gry * q0.y;
        float d1 = grx * q1.x + gry * q1.y;
        float d2 = grx * q2.x + gry * q2.y;
        float d3 = grx * q3.x + gry * q3.y;
        #pragma unroll
        for (int o = 16; o > 0; o >>= 1) {
            d0 += __shfl_xor_sync(0xFFFFFFFFu, d0, o);
            d1 += __shfl_xor_sync(0xFFFFFFFFu, d1, o);
            d2 += __shfl_xor_sync(0xFFFFFFFFu, d2, o);
            d3 += __shfl_xor_sync(0xFFFFFFFFu, d3, o);
        }
        float s0 = fmaf(d0, 0.5f, 0.5f);
        float s1 = fmaf(d1, 0.5f, 0.5f);
        float s2 = fmaf(d2, 0.5f, 0.5f);
        float s3 = fmaf(d3, 0.5f, 0.5f);
        rowsum += (s0 + s1) + (s2 + s3);
        float2 v0 = __half22float2(u32_as_h2(p0.y));
        float2 v1 = __half22float2(u32_as_h2(p1.y));
        float2 v2 = __half22float2(u32_as_h2(p2.y));
        float2 v3 = __half22float2(u32_as_h2(p3.y));
        fx = fmaf(s0, v0.x, fx);  fy = fmaf(s0, v0.y, fy);
        fx = fmaf(s1, v1.x, fx);  fy = fmaf(s1, v1.y, fy);
        fx = fmaf(s2, v2.x, fx);  fy = fmaf(s2, v2.y, fy);
        fx = fmaf(s3, v3.x, fx);  fy = fmaf(s3, v3.y, fy);
    }
    for (; j < end; j++) {
        int c = __ldg(g_ecol + j);
        uint2 p = __ldg(g_pack + (size_t)c * 32 + lane);
        float2 q = __half22float2(u32_as_h2(p.x));
        float d = grx * q.x + gry * q.y;
        #pragma unroll
        for (int o = 16; o > 0; o >>= 1) d += __shfl_xor_sync(0xFFFFFFFFu, d, o);
        float s = fmaf(d, 0.5f, 0.5f);
        rowsum += s;
        float2 v = __half22float2(u32_as_h2(p.y));
        fx = fmaf(s, v.x, fx);  fy = fmaf(s, v.y, fy);
    }

    float dinv = rowsum > 0.f ? 1.0f / rowsum : 0.f;
    fx *= dinv;
    fy *= dinv;

    // fine slice -> out (stacked: [acc(N,D)][user_fine(L,U,D)][item_fine(L,I,D)])
    size_t fpos;
    if (w < UU)
        fpos = (size_t)NN * DD + (size_t)layer * UU * DD + (size_t)w * DD;
    else
        fpos = (size_t)NN * DD + (size_t)LL * UU * DD + (size_t)layer * II * DD
             + (size_t)(w - UU) * DD;
    ((float2*)(out + fpos))[lane] = make_float2(fx, fy);

    float cx = gfull.x + fx, cy = gfull.y + fy;       // cur_next = gnn + fine
    ((float2*)(cur_new + (size_t)w * DD))[lane] = make_float2(cx, cy);

    float dr = g_dis[w];                               // curS_next = dis ⊙ cur_next
    ((float2*)(g_curS + (size_t)w * DD))[lane] = make_float2(cx * dr, cy * dr);

    float2* o = (float2*)(out + (size_t)w * DD);       // acc += cur_next
    float2 ov = o[lane];
    o[lane] = make_float2(ov.x + cx, ov.y + cy);
}

// ---------------- launch ----------------
extern "C" void kernel_launch(void* const* d_in, const int* in_sizes, int n_in,
                              void* d_out, int out_size) {
    const float* user_emb = (const float*)d_in[0];
    const float* item_emb = (const float*)d_in[1];
    const int*   rows     = (const int*)d_in[2];
    const int*   cols     = (const int*)d_in[3];
    float* out = (float*)d_out;

    void *p_deg, *p_curA, *p_curB, *p_curS;
    cudaGetSymbolAddress(&p_deg, g_deg);
    cudaGetSymbolAddress(&p_curA, g_curA);
    cudaGetSymbolAddress(&p_curB, g_curB);
    cudaGetSymbolAddress(&p_curS, g_curS);

    cudaStream_t s = 0;
    const int TB = 256;
    const int grid_E    = (EE + TB - 1) / TB;
    const int grid_N    = (NN + TB - 1) / TB;
    const int grid_ND   = (NN * DD + TB - 1) / TB;
    const int grid_RowW = (NN * 32 + TB - 1) / TB;

    cudaMemsetAsync(p_deg, 0, NN * sizeof(int), s);
    hist_kernel<<<grid_E, TB, 0, s>>>(rows);
    scan1_kernel<<<NBLK, SCAN_B, 0, s>>>();
    scan2_kernel<<<1, 256, 0, s>>>();
    scan3_kernel<<<grid_N, TB, 0, s>>>();
    scatter_kernel<<<grid_E, TB, 0, s>>>(rows, cols);
    init_kernel<<<grid_ND, TB, 0, s>>>(user_emb, item_emb, out);

    float* bufA = (float*)p_curA;
    float* bufB = (float*)p_curB;
    for (int l = 0; l < LL; l++) {
        layer1_kernel<<<grid_RowW, TB, 0, s>>>((const float*)p_curS, bufA);
        layer2_kernel<<<grid_RowW, TB, 0, s>>>(bufB, out, l);
        float* t = bufA; bufA = bufB; bufB = t;
    }
}

// round 12
// speedup vs baseline: 1.0791x; 1.0791x over previous
#include <cuda_runtime.h>
#include <cuda_fp16.h>
#include <math.h>

#define NN 150000
#define UU 100000
#define II 50000
#define DD 64
#define EE 2000000
#define LL 3
#define SCAN_B 1024
#define NBLK ((NN + SCAN_B - 1) / SCAN_B)   // 147

// -------- device scratch (no allocations allowed) --------
__device__ float   g_curA[NN * DD];
__device__ float   g_curB[NN * DD];
__device__ __half2 g_cursh[NN * 32];       // dis ⊙ cur, fp16 (layer1 gather operand)
__device__ float   g_gnn[NN * DD];
__device__ __half2 g_gnh[NN * 32];         // normalized gnn, fp16 (layer2 score gather)
__device__ float   g_invn[NN];
__device__ float   g_dis[NN];
__device__ int     g_deg[NN];
__device__ int     g_rowptr[NN + 1];
__device__ int     g_cursor[NN];
__device__ int     g_ecol[EE];
__device__ int     g_bsum[NBLK + 1];
__device__ int     g_boff[NBLK + 1];

// ---------------- setup kernels ----------------

__global__ void hist_kernel(const int* __restrict__ rows) {
    int e = blockIdx.x * blockDim.x + threadIdx.x;
    if (e < EE) atomicAdd(&g_deg[rows[e]], 1);
}

__global__ void scan1_kernel() {
    __shared__ int s[SCAN_B];
    int i = blockIdx.x * SCAN_B + threadIdx.x;
    int v = (i < NN) ? g_deg[i] : 0;
    if (i < NN) g_dis[i] = v > 0 ? rsqrtf((float)v) : 0.f;
    s[threadIdx.x] = v;
    __syncthreads();
    #pragma unroll
    for (int off = 1; off < SCAN_B; off <<= 1) {
        int t = (threadIdx.x >= off) ? s[threadIdx.x - off] : 0;
        __syncthreads();
        s[threadIdx.x] += t;
        __syncthreads();
    }
    if (i < NN) g_rowptr[i + 1] = s[threadIdx.x];
    if (threadIdx.x == SCAN_B - 1) g_bsum[blockIdx.x] = s[SCAN_B - 1];
}

__global__ void scan2_kernel() {
    __shared__ int s[256];
    int t = threadIdx.x;
    int v = (t < NBLK) ? g_bsum[t] : 0;
    s[t] = v;
    __syncthreads();
    #pragma unroll
    for (int off = 1; off < 256; off <<= 1) {
        int x = (t >= off) ? s[t - off] : 0;
        __syncthreads();
        s[t] += x;
        __syncthreads();
    }
    if (t < NBLK) g_boff[t] = s[t] - v;
}

__global__ void scan3_kernel() {
    int i = blockIdx.x * blockDim.x + threadIdx.x;
    if (i == 0) g_rowptr[0] = 0;
    if (i < NN) {
        int fin = g_rowptr[i + 1] + g_boff[i / SCAN_B];
        g_rowptr[i + 1] = fin;
        g_cursor[i] = fin - g_deg[i];
    }
}

__global__ void scatter_kernel(const int* __restrict__ rows, const int* __restrict__ cols) {
    int e = blockIdx.x * blockDim.x + threadIdx.x;
    if (e >= EE) return;
    int r = rows[e];
    int pos = atomicAdd(&g_cursor[r], 1);
    g_ecol[pos] = cols[e];
}

// cur = emb0; cursh = fp16(dis⊙emb0); out acc = emb0
// one thread per half2 slot (2 consecutive feature elements)
__global__ void init_kernel(const float* __restrict__ user_emb,
                            const float* __restrict__ item_emb,
                            float* __restrict__ out) {
    int i = blockIdx.x * blockDim.x + threadIdx.x;   // [0, NN*32)
    if (i >= NN * 32) return;
    int node = i >> 5;
    int e0 = node * DD + (i & 31) * 2;
    float v0 = (e0 < UU * DD) ? user_emb[e0] : item_emb[e0 - UU * DD];
    float v1 = (e0 + 1 < UU * DD) ? user_emb[e0 + 1] : item_emb[e0 + 1 - UU * DD];
    g_curA[e0] = v0;
    g_curA[e0 + 1] = v1;
    out[e0] = v0;
    out[e0 + 1] = v1;
    float dr = g_dis[node];
    g_cursh[i] = __floats2half2_rn(v0 * dr, v1 * dr);
}

// ---------------- per-layer kernels ----------------

// warp-per-row gather-sum (fp16 operand): gnn[r] = dis[r] * sum_e curS[c_e]
// epilogue: invn + fp16 normalized row
__global__ void __launch_bounds__(256)
layer1_kernel() {
    int w = (blockIdx.x * blockDim.x + threadIdx.x) >> 5;
    int lane = threadIdx.x & 31;
    if (w >= NN) return;
    int start = g_rowptr[w];
    int end   = g_rowptr[w + 1];
    float ax0 = 0.f, ay0 = 0.f, ax1 = 0.f, ay1 = 0.f;
    int j = start;
    for (; j + 3 < end; j += 4) {
        int c0 = __ldg(g_ecol + j);
        int c1 = __ldg(g_ecol + j + 1);
        int c2 = __ldg(g_ecol + j + 2);
        int c3 = __ldg(g_ecol + j + 3);
        float2 v0 = __half22float2(__ldg(g_cursh + (size_t)c0 * 32 + lane));
        float2 v1 = __half22float2(__ldg(g_cursh + (size_t)c1 * 32 + lane));
        float2 v2 = __half22float2(__ldg(g_cursh + (size_t)c2 * 32 + lane));
        float2 v3 = __half22float2(__ldg(g_cursh + (size_t)c3 * 32 + lane));
        ax0 += v0.x + v2.x;  ay0 += v0.y + v2.y;
        ax1 += v1.x + v3.x;  ay1 += v1.y + v3.y;
    }
    for (; j < end; j++) {
        int c = __ldg(g_ecol + j);
        float2 v = __half22float2(__ldg(g_cursh + (size_t)c * 32 + lane));
        ax0 += v.x;  ay0 += v.y;
    }
    float dr = g_dis[w];
    float ax = (ax0 + ax1) * dr;
    float ay = (ay0 + ay1) * dr;
    ((float2*)(g_gnn + (size_t)w * DD))[lane] = make_float2(ax, ay);
    float ss = ax * ax + ay * ay;
    #pragma unroll
    for (int o = 16; o > 0; o >>= 1) ss += __shfl_xor_sync(0xFFFFFFFFu, ss, o);
    float inv = 1.0f / fmaxf(sqrtf(ss), 1e-12f);
    if (lane == 0) g_invn[w] = inv;
    g_gnh[(size_t)w * 32 + lane] = __floats2half2_rn(ax * inv, ay * inv);
}

// warp-per-row fused: scores (fp16 c-side) + rowsum + fine + finalize
__global__ void __launch_bounds__(256)
layer2_kernel(const float* __restrict__ cur_old,
              float* __restrict__ cur_new,
              float* __restrict__ out, int layer) {
    int w = (blockIdx.x * blockDim.x + threadIdx.x) >> 5;
    int lane = threadIdx.x & 31;
    if (w >= NN) return;
    int start = g_rowptr[w];
    int end   = g_rowptr[w + 1];
    float2 gfull = ((const float2*)(g_gnn + (size_t)w * DD))[lane];
    float invr = g_invn[w];
    float grx = gfull.x * invr, gry = gfull.y * invr;

    float rowsum = 0.f, fx = 0.f, fy = 0.f;
    int j = start;
    for (; j + 3 < end; j += 4) {
        int c0 = __ldg(g_ecol + j);
        int c1 = __ldg(g_ecol + j + 1);
        int c2 = __ldg(g_ecol + j + 2);
        int c3 = __ldg(g_ecol + j + 3);
        float2 q0 = __half22float2(__ldg(g_gnh + (size_t)c0 * 32 + lane));
        float2 q1 = __half22float2(__ldg(g_gnh + (size_t)c1 * 32 + lane));
        float2 q2 = __half22float2(__ldg(g_gnh + (size_t)c2 * 32 + lane));
        float2 q3 = __half22float2(__ldg(g_gnh + (size_t)c3 * 32 + lane));
        float2 v0 = __ldg(((const float2*)(cur_old + (size_t)c0 * DD)) + lane);
        float2 v1 = __ldg(((const float2*)(cur_old + (size_t)c1 * DD)) + lane);
        float2 v2 = __ldg(((const float2*)(cur_old + (size_t)c2 * DD)) + lane);
        float2 v3 = __ldg(((const float2*)(cur_old + (size_t)c3 * DD)) + lane);
        float d0 = grx * q0.x + gry * q0.y;
        float d1 = grx * q1.x + gry * q1.y;
        float d2 = grx * q2.x + gry * q2.y;
        float d3 = grx * q3.x + gry * q3.y;
        #pragma unroll
        for (int o = 16; o > 0; o >>= 1) {
            d0 += __shfl_xor_sync(0xFFFFFFFFu, d0, o);
            d1 += __shfl_xor_sync(0xFFFFFFFFu, d1, o);
            d2 += __shfl_xor_sync(0xFFFFFFFFu, d2, o);
            d3 += __shfl_xor_sync(0xFFFFFFFFu, d3, o);
        }
        float s0 = fmaf(d0, 0.5f, 0.5f);
        float s1 = fmaf(d1, 0.5f, 0.5f);
        float s2 = fmaf(d2, 0.5f, 0.5f);
        float s3 = fmaf(d3, 0.5f, 0.5f);
        rowsum += (s0 + s1) + (s2 + s3);
        fx = fmaf(s0, v0.x, fx);  fy = fmaf(s0, v0.y, fy);
        fx = fmaf(s1, v1.x, fx);  fy = fmaf(s1, v1.y, fy);
        fx = fmaf(s2, v2.x, fx);  fy = fmaf(s2, v2.y, fy);
        fx = fmaf(s3, v3.x, fx);  fy = fmaf(s3, v3.y, fy);
    }
    for (; j < end; j++) {
        int c = __ldg(g_ecol + j);
        float2 q = __half22float2(__ldg(g_gnh + (size_t)c * 32 + lane));
        float2 v = __ldg(((const float2*)(cur_old + (size_t)c * DD)) + lane);
        float d = grx * q.x + gry * q.y;
        #pragma unroll
        for (int o = 16; o > 0; o >>= 1) d += __shfl_xor_sync(0xFFFFFFFFu, d, o);
        float s = fmaf(d, 0.5f, 0.5f);
        rowsum += s;
        fx = fmaf(s, v.x, fx);  fy = fmaf(s, v.y, fy);
    }

    float dinv = rowsum > 0.f ? 1.0f / rowsum : 0.f;
    fx *= dinv;
    fy *= dinv;

    // fine slice -> out (stacked: [acc(N,D)][user_fine(L,U,D)][item_fine(L,I,D)])
    size_t fpos;
    if (w < UU)
        fpos = (size_t)NN * DD + (size_t)layer * UU * DD + (size_t)w * DD;
    else
        fpos = (size_t)NN * DD + (size_t)LL * UU * DD + (size_t)layer * II * DD
             + (size_t)(w - UU) * DD;
    ((float2*)(out + fpos))[lane] = make_float2(fx, fy);

    float cx = gfull.x + fx, cy = gfull.y + fy;       // cur_next = gnn + fine
    ((float2*)(cur_new + (size_t)w * DD))[lane] = make_float2(cx, cy);

    float dr = g_dis[w];                               // curSh_next = fp16(dis ⊙ cur_next)
    g_cursh[(size_t)w * 32 + lane] = __floats2half2_rn(cx * dr, cy * dr);

    float2* o = (float2*)(out + (size_t)w * DD);       // acc += cur_next
    float2 ov = o[lane];
    o[lane] = make_float2(ov.x + cx, ov.y + cy);
}

// ---------------- launch ----------------
extern "C" void kernel_launch(void* const* d_in, const int* in_sizes, int n_in,
                              void* d_out, int out_size) {
    const float* user_emb = (const float*)d_in[0];
    const float* item_emb = (const float*)d_in[1];
    const int*   rows     = (const int*)d_in[2];
    const int*   cols     = (const int*)d_in[3];
    float* out = (float*)d_out;

    void *p_deg, *p_curA, *p_curB;
    cudaGetSymbolAddress(&p_deg, g_deg);
    cudaGetSymbolAddress(&p_curA, g_curA);
    cudaGetSymbolAddress(&p_curB, g_curB);

    cudaStream_t s = 0;
    const int TB = 256;
    const int grid_E    = (EE + TB - 1) / TB;
    const int grid_N    = (NN + TB - 1) / TB;
    const int grid_NH   = (NN * 32 + TB - 1) / TB;   // half2 slots
    const int grid_RowW = (NN * 32 + TB - 1) / TB;   // warp-per-row

    cudaMemsetAsync(p_deg, 0, NN * sizeof(int), s);
    hist_kernel<<<grid_E, TB, 0, s>>>(rows);
    scan1_kernel<<<NBLK, SCAN_B, 0, s>>>();
    scan2_kernel<<<1, 256, 0, s>>>();
    scan3_kernel<<<grid_N, TB, 0, s>>>();
    scatter_kernel<<<grid_E, TB, 0, s>>>(rows, cols);
    init_kernel<<<grid_NH, TB, 0, s>>>(user_emb, item_emb, out);

    float* bufA = (float*)p_curA;
    float* bufB = (float*)p_curB;
    for (int l = 0; l < LL; l++) {
        layer1_kernel<<<grid_RowW, TB, 0, s>>>();
        layer2_kernel<<<grid_RowW, TB, 0, s>>>(bufA, bufB, out, l);
        float* t = bufA; bufA = bufB; bufB = t;
    }
}